// round 1
// baseline (speedup 1.0000x reference)
#include <cuda_runtime.h>
#include <cuda_bf16.h>
#include <math.h>

// Problem constants
#define Bn   32
#define DQ   512
#define DK   512
#define NK   16
#define Hn   8
#define Tt   12
#define Nn   207
#define Cc   64
#define TNC  (Tt*Nn*Cc)      // 158976
#define Mrows (Bn*NK)        // 512
#define Ncols (Hn*DQ)        // 4096

// Device scratch (no cudaMalloc allowed)
__device__ float g_Xt[Mrows * DK];   // keys transposed: Xt[m][d], m = b*16+k  (1 MB)
__device__ float g_att[Mrows];       // logits accum -> softmax weights

// ---------------------------------------------------------------------------
// Kernel 0: transpose keys [B, DK, NK] -> Xt [B*NK, DK]; also zero att accum.
// One block per b. Fully coalesced both sides via smem tile.
// ---------------------------------------------------------------------------
__global__ void prep_kernel(const float* __restrict__ keys, float* __restrict__ Xt,
                            float* __restrict__ att) {
    __shared__ float s[32][17];
    int b = blockIdx.x;
    int tid = threadIdx.x;             // 512 threads
    if (b == 0 && tid < Mrows) att[tid] = 0.0f;

    int d_ld = tid >> 4;               // 0..31
    int k_ld = tid & 15;               // 0..15
    int k_st = tid >> 5;               // 0..15
    int d_st = tid & 31;               // 0..31
    const float* kb = keys + (size_t)b * DK * NK;
    float* xb = Xt + (size_t)b * NK * DK;

    for (int d0 = 0; d0 < DK; d0 += 32) {
        s[d_ld][k_ld] = kb[(d0 + d_ld) * NK + k_ld];
        __syncthreads();
        xb[k_st * DK + d0 + d_st] = s[d_st][k_st];
        __syncthreads();
    }
}

// ---------------------------------------------------------------------------
// Kernel A: fused GEMM + ReLU + Q-dot reduction.
//   Y[m, c] = sum_d Xt[m,d] * W[c,d]      (c = h*512+q, W flat [4096,512])
//   att[m] += sum_c relu(Y[m,c] + bias[c]) * query[b(m), c%512]
// Tiles: BM=64, BN=64, BK=16, 256 threads, 4x4 per thread.
// ---------------------------------------------------------------------------
#define BM 64
#define BN 64
#define BKt 16

__global__ __launch_bounds__(256)
void gemm_att_kernel(const float* __restrict__ Xt, const float* __restrict__ W,
                     const float* __restrict__ bias, const float* __restrict__ query,
                     float* __restrict__ att) {
    __shared__ float As[BKt][BM];
    __shared__ float Bs[BKt][BN];
    __shared__ float Qs[4][BN];      // 4 consecutive b's in this row tile
    __shared__ float biasS[BN];
    __shared__ float partS[BM];

    int tid = threadIdx.x;
    int tx = tid & 15;               // col group
    int ty = tid >> 4;               // row group
    int m0 = blockIdx.y * BM;        // row offset in [0,512)
    int c0 = blockIdx.x * BN;        // col offset in [0,4096), never crosses head
    int q0 = c0 & (DQ - 1);          // q offset within head
    int b0 = m0 >> 4;                // first b in tile (4 b's per 64 rows)

    // Stage Q tile and bias tile
    for (int i = tid; i < 4 * BN; i += 256)
        Qs[i >> 6][i & 63] = query[(b0 + (i >> 6)) * DQ + q0 + (i & 63)];
    if (tid < BN) biasS[tid] = bias[c0 + tid];
    if (tid < BM) partS[tid] = 0.0f;

    float acc[4][4] = {};

    int ml = tid >> 2;               // 0..63 : row/col loaded by this thread
    int k4 = (tid & 3) << 2;         // 0,4,8,12

    for (int kt = 0; kt < DK; kt += BKt) {
        float4 av = *(const float4*)&Xt[(m0 + ml) * DK + kt + k4];
        float4 bv = *(const float4*)&W[(size_t)(c0 + ml) * DK + kt + k4];
        __syncthreads();
        As[k4 + 0][ml] = av.x; As[k4 + 1][ml] = av.y;
        As[k4 + 2][ml] = av.z; As[k4 + 3][ml] = av.w;
        Bs[k4 + 0][ml] = bv.x; Bs[k4 + 1][ml] = bv.y;
        Bs[k4 + 2][ml] = bv.z; Bs[k4 + 3][ml] = bv.w;
        __syncthreads();

        #pragma unroll
        for (int kk = 0; kk < BKt; kk++) {
            float4 a = *(const float4*)&As[kk][ty << 2];
            float4 bb = *(const float4*)&Bs[kk][tx << 2];
            float ar[4] = {a.x, a.y, a.z, a.w};
            float br[4] = {bb.x, bb.y, bb.z, bb.w};
            #pragma unroll
            for (int i = 0; i < 4; i++)
                #pragma unroll
                for (int j = 0; j < 4; j++)
                    acc[i][j] = fmaf(ar[i], br[j], acc[i][j]);
        }
    }

    // Epilogue: relu + bias + weight by Q, reduce over columns
    float part[4] = {0.f, 0.f, 0.f, 0.f};
    #pragma unroll
    for (int i = 0; i < 4; i++) {
        int mloc = (ty << 2) + i;
        int bloc = mloc >> 4;        // 0..3
        #pragma unroll
        for (int j = 0; j < 4; j++) {
            float y = acc[i][j] + biasS[(tx << 2) + j];
            y = fmaxf(y, 0.0f);
            part[i] = fmaf(y, Qs[bloc][(tx << 2) + j], part[i]);
        }
    }
    #pragma unroll
    for (int i = 0; i < 4; i++)
        atomicAdd(&partS[(ty << 2) + i], part[i]);
    __syncthreads();
    if (tid < BM) atomicAdd(&att[m0 + tid], partS[tid]);
}

// ---------------------------------------------------------------------------
// Kernel B: softmax over NK=16 per batch row; logits scaled by 1/(H*sqrt(dk)).
// One warp per b.
// ---------------------------------------------------------------------------
__global__ void softmax_kernel(float* __restrict__ att) {
    int b = blockIdx.x;
    int lane = threadIdx.x;          // 32
    const float scale = 1.0f / (8.0f * 22.62741699796952f);  // 1/(H*sqrt(512))
    float v = (lane < NK) ? att[b * NK + lane] * scale : -INFINITY;
    float m = v;
    #pragma unroll
    for (int o = 16; o; o >>= 1) m = fmaxf(m, __shfl_xor_sync(0xffffffffu, m, o));
    float e = (lane < NK) ? __expf(v - m) : 0.0f;
    float s = e;
    #pragma unroll
    for (int o = 16; o; o >>= 1) s += __shfl_xor_sync(0xffffffffu, s, o);
    if (lane < NK) att[b * NK + lane] = e / s;
}

// ---------------------------------------------------------------------------
// Kernel C: out[b, i] = sum_e att[b,e] * V[b, i, e]   (i over T*N*C, e inner 16)
// HBM-bound: 325.6 MB read. Each thread: 4x float4 -> full sector utilization.
// ---------------------------------------------------------------------------
__global__ __launch_bounds__(256)
void weighted_v_kernel(const float* __restrict__ V, const float* __restrict__ att,
                       float* __restrict__ out) {
    __shared__ float aw[NK];
    int b = blockIdx.y;
    if (threadIdx.x < NK) aw[threadIdx.x] = att[b * NK + threadIdx.x];
    __syncthreads();
    int i = blockIdx.x * blockDim.x + threadIdx.x;
    if (i >= TNC) return;
    const float4* v4 = (const float4*)(V + ((size_t)b * TNC + i) * NK);
    float4 p0 = v4[0], p1 = v4[1], p2 = v4[2], p3 = v4[3];
    float s;
    s  = p0.x * aw[0]  + p0.y * aw[1]  + p0.z * aw[2]  + p0.w * aw[3];
    s += p1.x * aw[4]  + p1.y * aw[5]  + p1.z * aw[6]  + p1.w * aw[7];
    s += p2.x * aw[8]  + p2.y * aw[9]  + p2.z * aw[10] + p2.w * aw[11];
    s += p3.x * aw[12] + p3.y * aw[13] + p3.z * aw[14] + p3.w * aw[15];
    out[(size_t)b * TNC + i] = s;
}

// ---------------------------------------------------------------------------
extern "C" void kernel_launch(void* const* d_in, const int* in_sizes, int n_in,
                              void* d_out, int out_size) {
    const float *query = nullptr, *keys = nullptr, *V = nullptr,
                *W = nullptr, *bias = nullptr;
    for (int i = 0; i < n_in; i++) {
        switch (in_sizes[i]) {
            case Bn * DQ:            query = (const float*)d_in[i]; break;  // 16384
            case Bn * DK * NK:       keys  = (const float*)d_in[i]; break;  // 262144
            case Bn * TNC * NK:      V     = (const float*)d_in[i]; break;  // 81395712
            case Hn * DQ * DK:       W     = (const float*)d_in[i]; break;  // 2097152
            case Hn * DQ:            bias  = (const float*)d_in[i]; break;  // 4096
            default: break;
        }
    }
    float* out = (float*)d_out;

    float* Xt;  cudaGetSymbolAddress((void**)&Xt,  g_Xt);
    float* att; cudaGetSymbolAddress((void**)&att, g_att);

    // 0: transpose keys + zero att accumulator
    prep_kernel<<<Bn, 512>>>(keys, Xt, att);

    // A: fused GEMM + relu + Q-dot -> att logits
    dim3 gridA(Ncols / BN, Mrows / BM);   // (64, 8)
    gemm_att_kernel<<<gridA, 256>>>(Xt, W, bias, query, att);

    // B: softmax
    softmax_kernel<<<Bn, 32>>>(att);

    // C: att-weighted V reduction
    dim3 gridC(TNC / 256, Bn);            // (621, 32) — TNC divisible by 256
    weighted_v_kernel<<<gridC, 256>>>(V, att, out);
}

// round 2
// speedup vs baseline: 1.6155x; 1.6155x over previous
#include <cuda_runtime.h>
#include <cuda_bf16.h>
#include <math.h>
#include <stdint.h>

// Problem constants
#define Bn   32
#define DQ   512
#define DK   512
#define NK   16
#define Hn   8
#define Tt   12
#define Nn   207
#define Cc   64
#define TNC  (Tt*Nn*Cc)      // 158976
#define Mrows (Bn*NK)        // 512
#define Ncols (Hn*DQ)        // 4096

// Device scratch
__device__ float g_Xt[Mrows * DK];   // keys transposed: Xt[m][d], m = b*16+k
__device__ float g_att[Mrows];       // logits accum -> softmax weights

// ---------------------------------------------------------------------------
// Kernel 0: transpose keys [B, DK, NK] -> Xt [B*NK, DK]; zero att accum.
// ---------------------------------------------------------------------------
__global__ void prep_kernel(const float* __restrict__ keys, float* __restrict__ Xt,
                            float* __restrict__ att) {
    __shared__ float s[32][17];
    int b = blockIdx.x;
    int tid = threadIdx.x;             // 512 threads
    if (b == 0 && tid < Mrows) att[tid] = 0.0f;

    int d_ld = tid >> 4;               // 0..31
    int k_ld = tid & 15;               // 0..15
    int k_st = tid >> 5;               // 0..15
    int d_st = tid & 31;               // 0..31
    const float* kb = keys + (size_t)b * DK * NK;
    float* xb = Xt + (size_t)b * NK * DK;

    for (int d0 = 0; d0 < DK; d0 += 32) {
        s[d_ld][k_ld] = kb[(d0 + d_ld) * NK + k_ld];
        __syncthreads();
        xb[k_st * DK + d0 + d_st] = s[d_st][k_st];
        __syncthreads();
    }
}

// ---------------------------------------------------------------------------
// tf32 helpers
// ---------------------------------------------------------------------------
__device__ __forceinline__ float to_tf32(float x) {
    uint32_t u;
    asm("cvt.rna.tf32.f32 %0, %1;" : "=r"(u) : "f"(x));
    return __uint_as_float(u);
}

__device__ __forceinline__ void mma_tf32(float* c, const uint32_t* a,
                                         uint32_t b0, uint32_t b1) {
    asm volatile(
        "mma.sync.aligned.m16n8k8.row.col.f32.tf32.tf32.f32 "
        "{%0,%1,%2,%3}, {%4,%5,%6,%7}, {%8,%9}, {%0,%1,%2,%3};"
        : "+f"(c[0]), "+f"(c[1]), "+f"(c[2]), "+f"(c[3])
        : "r"(a[0]), "r"(a[1]), "r"(a[2]), "r"(a[3]), "r"(b0), "r"(b1));
}

// ---------------------------------------------------------------------------
// Kernel A: tensor-core GEMM (tf32) + fused ReLU/bias/Q-dot reduction.
//   Y[m, c] = sum_d Xt[m,d] * W[c,d]
//   att[m] += sum_c relu(Y[m,c] + bias[c]) * query[m>>4, c & 511]
// BM=128, BN=128, BK=32, 256 threads (8 warps: 2 M x 4 N), warp tile 64x32.
// ---------------------------------------------------------------------------
#define SSTR 36   // padded row stride (floats) -> conflict-free fragment LDS

__global__ __launch_bounds__(256)
void gemm_att_tc(const float* __restrict__ Xt, const float* __restrict__ W,
                 const float* __restrict__ bias, const float* __restrict__ query,
                 float* __restrict__ att) {
    __shared__ float As[128 * SSTR];
    __shared__ float Bs[128 * SSTR];
    __shared__ float Qs[8 * 128];
    __shared__ float biasS[128];
    __shared__ float partS[128];

    int tid  = threadIdx.x;
    int lane = tid & 31;
    int warp = tid >> 5;
    int warp_m = warp >> 2;        // 0..1  -> 64 rows
    int warp_n = warp & 3;         // 0..3  -> 32 cols
    int g   = lane >> 2;           // 0..7
    int tig = lane & 3;            // 0..3

    int c0 = blockIdx.x * 128;     // col tile in [0,4096), never crosses head
    int m0 = blockIdx.y * 128;     // row tile in [0,512)
    int q0 = c0 & (DQ - 1);
    int b0 = m0 >> 4;              // first batch in tile (8 per 128 rows)

    // Stage Q tile [8 b][128 q] and bias; zero partials
    for (int i = tid; i < 8 * 128; i += 256)
        Qs[i] = query[(b0 + (i >> 7)) * DQ + q0 + (i & 127)];
    if (tid < 128) { biasS[tid] = bias[c0 + tid]; partS[tid] = 0.0f; }

    float acc[4][4][4] = {};       // [mtile][ntile][frag]

    int lr = tid >> 3;             // 0..31 row within 32-row chunk
    int lc = (tid & 7) << 2;       // 0,4,...,28 col (float4)

    for (int kt = 0; kt < DK; kt += 32) {
        // prefetch global
        float4 av[4], bv[4];
        #pragma unroll
        for (int rr = 0; rr < 4; rr++) {
            int r = lr + rr * 32;
            av[rr] = *(const float4*)&Xt[(size_t)(m0 + r) * DK + kt + lc];
            bv[rr] = *(const float4*)&W [(size_t)(c0 + r) * DK + kt + lc];
        }
        __syncthreads();   // previous iter consumers done
        #pragma unroll
        for (int rr = 0; rr < 4; rr++) {
            int r = lr + rr * 32;
            float* pa = &As[r * SSTR + lc];
            pa[0] = to_tf32(av[rr].x); pa[1] = to_tf32(av[rr].y);
            pa[2] = to_tf32(av[rr].z); pa[3] = to_tf32(av[rr].w);
            float* pb = &Bs[r * SSTR + lc];
            pb[0] = to_tf32(bv[rr].x); pb[1] = to_tf32(bv[rr].y);
            pb[2] = to_tf32(bv[rr].z); pb[3] = to_tf32(bv[rr].w);
        }
        __syncthreads();   // tile ready

        #pragma unroll
        for (int ks = 0; ks < 4; ks++) {
            int k = ks * 8 + tig;
            // A fragments: 4 m-tiles of 16 rows
            uint32_t a[4][4];
            #pragma unroll
            for (int mt = 0; mt < 4; mt++) {
                int mbase = warp_m * 64 + mt * 16 + g;
                a[mt][0] = __float_as_uint(As[(mbase    ) * SSTR + k    ]);
                a[mt][1] = __float_as_uint(As[(mbase + 8) * SSTR + k    ]);
                a[mt][2] = __float_as_uint(As[(mbase    ) * SSTR + k + 4]);
                a[mt][3] = __float_as_uint(As[(mbase + 8) * SSTR + k + 4]);
            }
            #pragma unroll
            for (int nt = 0; nt < 4; nt++) {
                int nbase = warp_n * 32 + nt * 8 + g;
                uint32_t b0r = __float_as_uint(Bs[nbase * SSTR + k    ]);
                uint32_t b1r = __float_as_uint(Bs[nbase * SSTR + k + 4]);
                #pragma unroll
                for (int mt = 0; mt < 4; mt++)
                    mma_tf32(acc[mt][nt], a[mt], b0r, b1r);
            }
        }
    }

    // Epilogue: bias + relu + Q-weight, reduce per row
    #pragma unroll
    for (int mt = 0; mt < 4; mt++) {
        int mlo = warp_m * 64 + mt * 16 + g;   // local row (low half)
        int mhi = mlo + 8;
        const float* q_lo = &Qs[(mlo >> 4) * 128];
        const float* q_hi = &Qs[(mhi >> 4) * 128];
        float p_lo = 0.0f, p_hi = 0.0f;
        #pragma unroll
        for (int nt = 0; nt < 4; nt++) {
            int cl = warp_n * 32 + nt * 8 + 2 * tig;
            float bi0 = biasS[cl], bi1 = biasS[cl + 1];
            p_lo = fmaf(fmaxf(acc[mt][nt][0] + bi0, 0.0f), q_lo[cl],     p_lo);
            p_lo = fmaf(fmaxf(acc[mt][nt][1] + bi1, 0.0f), q_lo[cl + 1], p_lo);
            p_hi = fmaf(fmaxf(acc[mt][nt][2] + bi0, 0.0f), q_hi[cl],     p_hi);
            p_hi = fmaf(fmaxf(acc[mt][nt][3] + bi1, 0.0f), q_hi[cl + 1], p_hi);
        }
        // reduce over the 4 lanes (tig) sharing each row
        p_lo += __shfl_xor_sync(0xffffffffu, p_lo, 1);
        p_lo += __shfl_xor_sync(0xffffffffu, p_lo, 2);
        p_hi += __shfl_xor_sync(0xffffffffu, p_hi, 1);
        p_hi += __shfl_xor_sync(0xffffffffu, p_hi, 2);
        if (tig == 0) {
            atomicAdd(&partS[mlo], p_lo);
            atomicAdd(&partS[mhi], p_hi);
        }
    }
    __syncthreads();
    if (tid < 128) atomicAdd(&att[m0 + tid], partS[tid]);
}

// ---------------------------------------------------------------------------
// Kernel B: softmax over NK=16 per batch; logits scaled by 1/(H*sqrt(dk)).
// ---------------------------------------------------------------------------
__global__ void softmax_kernel(float* __restrict__ att) {
    int b = blockIdx.x;
    int lane = threadIdx.x;
    const float scale = 1.0f / (8.0f * 22.62741699796952f);
    float v = (lane < NK) ? att[b * NK + lane] * scale : -INFINITY;
    float m = v;
    #pragma unroll
    for (int o = 16; o; o >>= 1) m = fmaxf(m, __shfl_xor_sync(0xffffffffu, m, o));
    float e = (lane < NK) ? __expf(v - m) : 0.0f;
    float s = e;
    #pragma unroll
    for (int o = 16; o; o >>= 1) s += __shfl_xor_sync(0xffffffffu, s, o);
    if (lane < NK) att[b * NK + lane] = e / s;
}

// ---------------------------------------------------------------------------
// Kernel C: out[b, i] = sum_e att[b,e] * V[b, i, e]  (HBM-bound, ~79% DRAM)
// ---------------------------------------------------------------------------
__global__ __launch_bounds__(256)
void weighted_v_kernel(const float* __restrict__ V, const float* __restrict__ att,
                       float* __restrict__ out) {
    __shared__ float aw[NK];
    int b = blockIdx.y;
    if (threadIdx.x < NK) aw[threadIdx.x] = att[b * NK + threadIdx.x];
    __syncthreads();
    int i = blockIdx.x * blockDim.x + threadIdx.x;
    if (i >= TNC) return;
    const float4* v4 = (const float4*)(V + ((size_t)b * TNC + i) * NK);
    float4 p0 = v4[0], p1 = v4[1], p2 = v4[2], p3 = v4[3];
    float s;
    s  = p0.x * aw[0]  + p0.y * aw[1]  + p0.z * aw[2]  + p0.w * aw[3];
    s += p1.x * aw[4]  + p1.y * aw[5]  + p1.z * aw[6]  + p1.w * aw[7];
    s += p2.x * aw[8]  + p2.y * aw[9]  + p2.z * aw[10] + p2.w * aw[11];
    s += p3.x * aw[12] + p3.y * aw[13] + p3.z * aw[14] + p3.w * aw[15];
    out[(size_t)b * TNC + i] = s;
}

// ---------------------------------------------------------------------------
extern "C" void kernel_launch(void* const* d_in, const int* in_sizes, int n_in,
                              void* d_out, int out_size) {
    const float *query = nullptr, *keys = nullptr, *V = nullptr,
                *W = nullptr, *bias = nullptr;
    for (int i = 0; i < n_in; i++) {
        switch (in_sizes[i]) {
            case Bn * DQ:            query = (const float*)d_in[i]; break;
            case Bn * DK * NK:       keys  = (const float*)d_in[i]; break;
            case Bn * TNC * NK:      V     = (const float*)d_in[i]; break;
            case Hn * DQ * DK:       W     = (const float*)d_in[i]; break;
            case Hn * DQ:            bias  = (const float*)d_in[i]; break;
            default: break;
        }
    }
    float* out = (float*)d_out;

    float* Xt;  cudaGetSymbolAddress((void**)&Xt,  g_Xt);
    float* att; cudaGetSymbolAddress((void**)&att, g_att);

    prep_kernel<<<Bn, 512>>>(keys, Xt, att);

    dim3 gridA(Ncols / 128, Mrows / 128);   // (32, 4)
    gemm_att_tc<<<gridA, 256>>>(Xt, W, bias, query, att);

    softmax_kernel<<<Bn, 32>>>(att);

    dim3 gridC(TNC / 256, Bn);              // (621, 32)
    weighted_v_kernel<<<gridC, 256>>>(V, att, out);
}